// round 12
// baseline (speedup 1.0000x reference)
#include <cuda_runtime.h>
#include <math.h>

#define NHIT 80000
#define KOBJ 512
#define GRID 157
#define THR  256
#define NT   (GRID * THR)      // 40192 threads; each owns hits i and i+NT
#define NPAD (2 * NT)          // 80384 (pads inert)
#define EPSF 1e-9f

// ---------------- scratch (device globals; zero at load, reset after use) ----------
__device__ float4 g_hit[NPAD];                 // x, y, q, t_idx (int bits)
__device__ float4 g_A[KOBJ];                   // -2ax, -2ay, |a|^2+1e-6, wrep
__device__ float  g_watt[KOBJ];                // q_a/(cnt+eps)
__device__ float  g_beta_a[KOBJ];
__device__ unsigned long long g_amax[KOBJ];    // packed (beta_bits<<32 | ~idx)
__device__ int    g_cnt[KOBJ];
__device__ float2 g_numden[KOBJ];              // payload num, den
__device__ float  g_pairsum, g_noise_sum, g_noise_cnt, g_cc_sum;
__device__ unsigned g_done_a, g_flag, g_done_b;

__device__ __forceinline__ float clampb(float b) {
    return fminf(fmaxf(b, 1e-6f), 1.0f - 1e-6f);
}
__device__ __forceinline__ float softclip_f(float x, float c) {
    x = x * (1.0f / c);
    if (x > 1.0f) x = __logf(x + 1.0f);
    return x * c;
}
__device__ __forceinline__ float huber_f(float x, float d) {
    float ax = fabsf(x);
    return ax < d ? x * x : d * d + 2.0f * d * (ax - d);
}
__device__ __forceinline__ float sqapx(float x) {
    float s; asm("sqrt.approx.f32 %0, %1;" : "=f"(s) : "f"(x)); return s;
}

// ---------------- phase A body: one hit ----------------
__device__ __forceinline__ void process_hit(int i, bool valid,
        const float* __restrict__ pb,  const float* __restrict__ cc,
        const float* __restrict__ pe,  const float* __restrict__ pp,
        const float* __restrict__ pt,  const float* __restrict__ pid,
        const int*   __restrict__ tix, const float* __restrict__ te,
        const float* __restrict__ tp,  const float* __restrict__ tt,
        float& ns, float& ncnt, float& ccs) {
    if (!valid) { g_hit[i] = make_float4(0.f, 0.f, 0.f, __int_as_float(-1)); return; }
    float  braw = pb[i];
    int    t    = tix[i];
    float2 ccv  = ((const float2*)cc)[i];
    float  pev  = pe[i];
    float2 ppv  = ((const float2*)pp)[i];
    float  ptv  = pt[i];
    float  tev  = te[i];
    float2 tpv  = ((const float2*)tp)[i];
    float  ttv  = tt[i];
    float2 pid0 = ((const float2*)pid)[3 * i];
    float2 pid1 = ((const float2*)pid)[3 * i + 1];
    float2 pid2 = ((const float2*)pid)[3 * i + 2];

    float beta = clampb(braw);
    float lg = __logf(__fdividef(1.0f + beta, 1.0f - beta));
    float q = fmaf(0.25f * lg, lg, 0.1f);
    g_hit[i] = make_float4(ccv.x, ccv.y, q, __int_as_float(t));
    ccs += ccv.x * ccv.x + ccv.y * ccv.y;

    float ed = fabsf(tev - pev);
    float el = softclip_f(fmaf(10.0f, __expf(-0.1f * ed * ed), 0.01f * ed), 10.0f);
    float dx = tpv.x - ppv.x, dy = tpv.y - ppv.y;
    float pl = softclip_f(huber_f(sqrtf(fmaf(dx, dx, dy * dy) * 0.01f + 0.01f), 10.0f), 3.0f);
    float tl = softclip_f(huber_f(ttv - ptv, 2.0f), 6.0f);
    float s2 = pid0.x * pid0.x + pid0.y * pid0.y + pid1.x * pid1.x
             + pid1.y * pid1.y + pid2.x * pid2.x + pid2.y * pid2.y;
    float cl = 1e-8f * (s2 * (1.0f / 6.0f));
    float payload = el + pl + tl + cl;
    float w = tev > 10.0f ? 1.0f : fmaxf((tev - 0.5f) * (1.0f / 9.5f), 0.0f);
    float pw = beta * w;

    if (t >= 0) {
        atomicAdd(&g_cnt[t], 1);
        unsigned long long key =
            (((unsigned long long)__float_as_uint(beta)) << 32) |
            (unsigned long long)(0xFFFFFFFFu - (unsigned)i);
        atomicMax(&g_amax[t], key);
        asm volatile("red.global.add.v2.f32 [%0], {%1, %2};"
                     :: "l"(&g_numden[t]), "f"(payload * pw), "f"(pw) : "memory");
    } else {
        ns += beta; ncnt += 1.0f;
    }
}

// ---------------- fused kernel ----------------
__global__ void __launch_bounds__(THR, 2) k_fused(
        const float* __restrict__ pb,  const float* __restrict__ cc,
        const float* __restrict__ pe,  const float* __restrict__ pp,
        const float* __restrict__ pt,  const float* __restrict__ pid,
        const int*   __restrict__ tix, const float* __restrict__ te,
        const float* __restrict__ tp,  const float* __restrict__ tt,
        float* __restrict__ out) {
    __shared__ float4 sA[KOBJ];          // 8KB
    __shared__ float  s_red[2 * THR];
    __shared__ unsigned s_last;

    const int t  = threadIdx.x;
    const int i0 = blockIdx.x * THR + t;     // < 40192 < NHIT: always valid
    const int i1 = i0 + NT;

    // ================= phase A: per-hit =================
    float ns = 0.f, ncnt = 0.f, ccs = 0.f;
    process_hit(i0, true,        pb, cc, pe, pp, pt, pid, tix, te, tp, tt, ns, ncnt, ccs);
    process_hit(i1, i1 < NHIT,   pb, cc, pe, pp, pt, pid, tix, te, tp, tt, ns, ncnt, ccs);
    #pragma unroll
    for (int o = 16; o > 0; o >>= 1) {
        ns   += __shfl_down_sync(0xFFFFFFFF, ns, o);
        ncnt += __shfl_down_sync(0xFFFFFFFF, ncnt, o);
        ccs  += __shfl_down_sync(0xFFFFFFFF, ccs, o);
    }
    if ((t & 31) == 0) {
        if (ns != 0.0f || ncnt != 0.0f) { atomicAdd(&g_noise_sum, ns); atomicAdd(&g_noise_cnt, ncnt); }
        atomicAdd(&g_cc_sum, ccs);
    }

    // ================= grid sync: last block builds A-table =================
    __threadfence();
    if (t == 0) s_last = atomicAdd(&g_done_a, 1u);
    __syncthreads();
    if (s_last == GRID - 1) {
        #pragma unroll
        for (int kk = 0; kk < 2; kk++) {
            int k = t + kk * THR;
            int c = g_cnt[k];
            if (c > 0) {
                unsigned idx = 0xFFFFFFFFu - (unsigned)(g_amax[k] & 0xFFFFFFFFull);
                float b = clampb(pb[idx]);
                float lg = __logf(__fdividef(1.0f + b, 1.0f - b));
                float qa = fmaf(0.25f * lg, lg, 0.1f);
                float2 ccv = ((const float2*)cc)[idx];
                float fc = (float)c;
                g_A[k] = make_float4(-2.0f * ccv.x, -2.0f * ccv.y,
                                     fmaf(ccv.x, ccv.x, ccv.y * ccv.y) + 1e-6f,
                                     qa / ((float)NHIT - fc + EPSF));
                g_watt[k]   = qa / (fc + EPSF);
                g_beta_a[k] = b;
            } else {
                g_A[k] = make_float4(0.f, 0.f, 1e-6f, 0.f);   // wrep=0: inert
                g_watt[k] = 0.f; g_beta_a[k] = 1.f;
            }
        }
        __threadfence();
        __syncthreads();
        if (t == 0) { g_done_a = 0u; atomicExch(&g_flag, 1u); }
    } else {
        if (t == 0) {
            while (((volatile unsigned*)&g_flag)[0] == 0u) __nanosleep(64);
        }
        __syncthreads();
    }
    __threadfence();   // acquire: order table reads after flag

    // ================= phase B: flattened N x K =================
    sA[t]       = g_A[t];
    sA[t + THR] = g_A[t + THR];
    __syncthreads();

    float4 h0 = g_hit[i0];
    float4 h1 = g_hit[i1];
    const float hx0 = h0.x, hy0 = h0.y, h20 = fmaf(hx0, hx0, hy0 * hy0);
    const float hx1 = h1.x, hy1 = h1.y, h21 = fmaf(hx1, hx1, hy1 * hy1);
    float acc0 = 0.f, acc1 = 0.f;

    #pragma unroll 8
    for (int k = 0; k < KOBJ; k++) {
        float4 a = sA[k];                     // uniform k -> broadcast LDS.128
        float v0 = fmaf(a.x, hx0, a.z);
        v0 = fmaf(a.y, hy0, v0);
        float d0 = v0 + h20;                  // = |h0-a|^2 + 1e-6
        float s0 = __saturatef(1.0f - sqapx(d0));
        acc0 = fmaf(s0, a.w, acc0);

        float v1 = fmaf(a.x, hx1, a.z);
        v1 = fmaf(a.y, hy1, v1);
        float d1 = v1 + h21;
        float s1 = __saturatef(1.0f - sqapx(d1));
        acc1 = fmaf(s1, a.w, acc1);
    }

    // member corrections (same expanded formula -> exact cancellation)
    int ti0 = __float_as_int(h0.w);
    if (ti0 >= 0) {
        float4 a = sA[ti0];
        float v = fmaf(a.x, hx0, a.z); v = fmaf(a.y, hy0, v);
        float d2e = v + h20;
        float s = __saturatef(1.0f - sqapx(d2e));
        acc0 = fmaf(-s, a.w, acc0);
        acc0 = fmaf(d2e - 1e-6f, g_watt[ti0], acc0);
    }
    int ti1 = __float_as_int(h1.w);
    if (ti1 >= 0) {
        float4 a = sA[ti1];
        float v = fmaf(a.x, hx1, a.z); v = fmaf(a.y, hy1, v);
        float d2e = v + h21;
        float s = __saturatef(1.0f - sqapx(d2e));
        acc1 = fmaf(-s, a.w, acc1);
        acc1 = fmaf(d2e - 1e-6f, g_watt[ti1], acc1);
    }
    float contrib = h0.z * acc0 + h1.z * acc1;
    #pragma unroll
    for (int o = 16; o > 0; o >>= 1)
        contrib += __shfl_down_sync(0xFFFFFFFF, contrib, o);
    if ((t & 31) == 0) atomicAdd(&g_pairsum, contrib);

    // ================= finalize in last-finishing block =================
    __threadfence();
    if (t == 0) s_last = atomicAdd(&g_done_b, 1u);
    __syncthreads();
    if (s_last != GRID - 1) return;

    float obj = 0.f, has = 0.f;
    #pragma unroll
    for (int kk = 0; kk < 2; kk++) {
        int k = t + kk * THR;
        int c = g_cnt[k];
        if (c > 0) {
            has += 1.0f;
            float2 nd = g_numden[k];
            obj += nd.x / (nd.y + EPSF) + (1.0f - g_beta_a[k]);
        }
        g_amax[k] = 0ull; g_cnt[k] = 0;
        g_numden[k] = make_float2(0.f, 0.f);
    }
    s_red[t] = obj; s_red[t + THR] = has;
    __syncthreads();
    #pragma unroll
    for (int o = THR / 2; o > 0; o >>= 1) {
        if (t < o) { s_red[t] += s_red[t + o]; s_red[t + THR] += s_red[t + THR + o]; }
        __syncthreads();
    }
    if (t == 0) {
        float n_obj = s_red[THR] + EPSF;
        float total = (s_red[0] + g_pairsum) / n_obj
                    + g_noise_sum / (g_noise_cnt + EPSF)
                    + 0.001f * g_cc_sum * (1.0f / (float)(NHIT * 2));
        out[0] = total;
        g_pairsum = 0.f; g_noise_sum = 0.f; g_noise_cnt = 0.f; g_cc_sum = 0.f;
        g_flag = 0u; g_done_b = 0u;
    }
}

// ---------------- launch ----------------
extern "C" void kernel_launch(void* const* d_in, const int* in_sizes, int n_in,
                              void* d_out, int out_size) {
    const float* pb  = (const float*)d_in[0];
    const float* cc  = (const float*)d_in[1];
    const float* pe  = (const float*)d_in[2];
    const float* pp  = (const float*)d_in[3];
    const float* pt  = (const float*)d_in[4];
    const float* pid = (const float*)d_in[5];
    const int*   tix = (const int*)  d_in[6];
    const float* te  = (const float*)d_in[7];
    const float* tp  = (const float*)d_in[8];
    const float* tt  = (const float*)d_in[9];

    k_fused<<<GRID, THR>>>(pb, cc, pe, pp, pt, pid, tix, te, tp, tt, (float*)d_out);
}

// round 13
// speedup vs baseline: 1.0471x; 1.0471x over previous
#include <cuda_runtime.h>
#include <math.h>

#define NHIT 80000
#define KOBJ 512
#define HBLK 313               // 313*256 = 80128 threads
#define EPSF 1e-9f

// ---------------- scratch (device globals; zero at load, reset after use) ----------
__device__ float4 g_hit[NHIT];                 // x, y, q, t_idx (int bits)
__device__ float4 g_A[KOBJ];                   // -2ax, -2ay, |a|^2+1e-6, wrep
__device__ float  g_watt[KOBJ];                // q_a/(cnt+eps)
__device__ float  g_beta_a[KOBJ];
__device__ unsigned long long g_amax[KOBJ];    // packed (beta_bits<<32 | ~idx)
__device__ int    g_cnt[KOBJ];
__device__ float2 g_numden[KOBJ];              // payload num, den
__device__ float  g_pairsum, g_noise_sum, g_noise_cnt, g_cc_sum;
__device__ unsigned g_done_h, g_done_p;

__device__ __forceinline__ float clampb(float b) {
    return fminf(fmaxf(b, 1e-6f), 1.0f - 1e-6f);
}
__device__ __forceinline__ float softclip_f(float x, float c) {
    x = x * (1.0f / c);
    if (x > 1.0f) x = __logf(x + 1.0f);
    return x * c;
}
__device__ __forceinline__ float huber_f(float x, float d) {
    float ax = fabsf(x);
    return ax < d ? x * x : d * d + 2.0f * d * (ax - d);
}
__device__ __forceinline__ float sqapx(float x) {
    float s; asm("sqrt.approx.f32 %0, %1;" : "=f"(s) : "f"(x)); return s;
}

// ---------------- kernel 1: per-hit pass + fused expanded-A-table build ------------
__global__ void __launch_bounds__(256) k_hits(
        const float* __restrict__ pb,  const float* __restrict__ cc,
        const float* __restrict__ pe,  const float* __restrict__ pp,
        const float* __restrict__ pt,  const float* __restrict__ pid,
        const int*   __restrict__ tix, const float* __restrict__ te,
        const float* __restrict__ tp,  const float* __restrict__ tt) {
    __shared__ unsigned s_last;
    int i = blockIdx.x * blockDim.x + threadIdx.x;
    float ns = 0.0f, ncnt = 0.0f, ccs = 0.0f;
    if (i < NHIT) {   // warp-uniform (80000 % 32 == 0)
        float  braw = pb[i];
        int    t    = tix[i];
        float2 ccv  = ((const float2*)cc)[i];
        float  pev  = pe[i];
        float2 ppv  = ((const float2*)pp)[i];
        float  ptv  = pt[i];
        float  tev  = te[i];
        float2 tpv  = ((const float2*)tp)[i];
        float  ttv  = tt[i];
        float2 pid0 = ((const float2*)pid)[3 * i];
        float2 pid1 = ((const float2*)pid)[3 * i + 1];
        float2 pid2 = ((const float2*)pid)[3 * i + 2];

        float beta = clampb(braw);
        float lg = __logf(__fdividef(1.0f + beta, 1.0f - beta));
        float q = fmaf(0.25f * lg, lg, 0.1f);
        g_hit[i] = make_float4(ccv.x, ccv.y, q, __int_as_float(t));
        ccs = ccv.x * ccv.x + ccv.y * ccv.y;

        float ed = fabsf(tev - pev);
        float el = softclip_f(fmaf(10.0f, __expf(-0.1f * ed * ed), 0.01f * ed), 10.0f);
        float dx = tpv.x - ppv.x, dy = tpv.y - ppv.y;
        float pl = softclip_f(huber_f(sqrtf(fmaf(dx, dx, dy * dy) * 0.01f + 0.01f), 10.0f), 3.0f);
        float tl = softclip_f(huber_f(ttv - ptv, 2.0f), 6.0f);
        float s2 = pid0.x * pid0.x + pid0.y * pid0.y + pid1.x * pid1.x
                 + pid1.y * pid1.y + pid2.x * pid2.x + pid2.y * pid2.y;
        float cl = 1e-8f * (s2 * (1.0f / 6.0f));
        float payload = el + pl + tl + cl;
        float w = tev > 10.0f ? 1.0f : fmaxf((tev - 0.5f) * (1.0f / 9.5f), 0.0f);
        float pw = beta * w;

        if (t >= 0) {
            atomicAdd(&g_cnt[t], 1);
            unsigned long long key =
                (((unsigned long long)__float_as_uint(beta)) << 32) |
                (unsigned long long)(0xFFFFFFFFu - (unsigned)i);
            atomicMax(&g_amax[t], key);
            asm volatile("red.global.add.v2.f32 [%0], {%1, %2};"
                         :: "l"(&g_numden[t]), "f"(payload * pw), "f"(pw) : "memory");
        } else {
            ns = beta; ncnt = 1.0f;
        }
    }
    #pragma unroll
    for (int o = 16; o > 0; o >>= 1) {
        ns   += __shfl_down_sync(0xFFFFFFFF, ns, o);
        ncnt += __shfl_down_sync(0xFFFFFFFF, ncnt, o);
        ccs  += __shfl_down_sync(0xFFFFFFFF, ccs, o);
    }
    if ((threadIdx.x & 31) == 0) {
        if (ns != 0.0f || ncnt != 0.0f) { atomicAdd(&g_noise_sum, ns); atomicAdd(&g_noise_cnt, ncnt); }
        atomicAdd(&g_cc_sum, ccs);
    }

    // ---- last block builds the expanded A-table ----
    __threadfence();
    if (threadIdx.x == 0) s_last = atomicAdd(&g_done_h, 1u);
    __syncthreads();
    if (s_last != gridDim.x - 1) return;

    #pragma unroll
    for (int kk = 0; kk < 2; kk++) {
        int k = threadIdx.x + kk * 256;
        int c = g_cnt[k];
        if (c > 0) {
            unsigned idx = 0xFFFFFFFFu - (unsigned)(g_amax[k] & 0xFFFFFFFFull);
            float b = clampb(pb[idx]);
            float lg = __logf(__fdividef(1.0f + b, 1.0f - b));
            float qa = fmaf(0.25f * lg, lg, 0.1f);
            float2 ccv = ((const float2*)cc)[idx];
            float fc = (float)c;
            g_A[k] = make_float4(-2.0f * ccv.x, -2.0f * ccv.y,
                                 fmaf(ccv.x, ccv.x, ccv.y * ccv.y) + 1e-6f,
                                 qa / ((float)NHIT - fc + EPSF));
            g_watt[k]   = qa / (fc + EPSF);
            g_beta_a[k] = b;
        } else {
            g_A[k] = make_float4(0.f, 0.f, 1e-6f, 0.f);   // wrep=0: inert
            g_watt[k] = 0.f; g_beta_a[k] = 1.f;
        }
    }
    if (threadIdx.x == 0) g_done_h = 0u;   // reset for next graph replay
}

// ---------------- kernel 2: hit-parallel flattened N x K (expanded form) ----------
__global__ void __launch_bounds__(256, 4) k_rep(float* __restrict__ out) {
    __shared__ float4 sA[KOBJ];          // 8KB: all condensation points
    __shared__ float s_red[512];
    __shared__ unsigned s_last;

    const int t = threadIdx.x;
    sA[t]       = g_A[t];
    sA[t + 256] = g_A[t + 256];
    __syncthreads();

    const int i = blockIdx.x * blockDim.x + t;
    float contrib = 0.0f;
    if (i < NHIT) {    // warp-uniform
        float4 h = g_hit[i];
        const float hx = h.x, hy = h.y;
        const float h2 = fmaf(hx, hx, hy * hy);
        float acc = 0.0f;

        #pragma unroll 8
        for (int k = 0; k < KOBJ; k++) {
            float4 a = sA[k];            // uniform k -> broadcast LDS.128
            float v = fmaf(a.x, hx, a.z);      // -2ax*hx + |a|^2 + eps
            v = fmaf(a.y, hy, v);              // + -2ay*hy
            float d2 = v + h2;                 // = |h-a|^2 + eps
            float s = __saturatef(1.0f - sqapx(d2));
            acc = fmaf(s, a.w, acc);
        }

        // member terms: remove own-object repulsion (exact cancel), add attraction
        int ti = __float_as_int(h.w);
        if (ti >= 0) {
            float4 a = sA[ti];
            float v = fmaf(a.x, hx, a.z);
            v = fmaf(a.y, hy, v);
            float d2 = v + h2;
            float s = __saturatef(1.0f - sqapx(d2));
            acc = fmaf(-s, a.w, acc);
            acc = fmaf(d2 - 1e-6f, g_watt[ti], acc);
        }
        contrib = h.z * acc;
    }
    #pragma unroll
    for (int o = 16; o > 0; o >>= 1)
        contrib += __shfl_down_sync(0xFFFFFFFF, contrib, o);
    if ((t & 31) == 0) atomicAdd(&g_pairsum, contrib);

    // ---- last block finalizes + resets scratch for next graph replay ----
    __threadfence();
    if (t == 0) s_last = atomicAdd(&g_done_p, 1u);
    __syncthreads();
    if (s_last != gridDim.x - 1) return;

    float obj = 0.f, has = 0.f;
    #pragma unroll
    for (int kk = 0; kk < 2; kk++) {
        int k = t + kk * 256;
        int c = g_cnt[k];
        if (c > 0) {
            has += 1.0f;
            float2 nd = g_numden[k];
            obj += nd.x / (nd.y + EPSF) + (1.0f - g_beta_a[k]);
        }
        g_amax[k] = 0ull; g_cnt[k] = 0;
        g_numden[k] = make_float2(0.f, 0.f);
    }
    s_red[t] = obj; s_red[t + 256] = has;
    __syncthreads();
    #pragma unroll
    for (int o = 128; o > 0; o >>= 1) {
        if (t < o) { s_red[t] += s_red[t + o]; s_red[t + 256] += s_red[t + 256 + o]; }
        __syncthreads();
    }
    if (t == 0) {
        float n_obj = s_red[256] + EPSF;
        float total = (s_red[0] + g_pairsum) / n_obj
                    + g_noise_sum / (g_noise_cnt + EPSF)
                    + 0.001f * g_cc_sum * (1.0f / (float)(NHIT * 2));
        out[0] = total;
        g_pairsum = 0.f; g_noise_sum = 0.f; g_noise_cnt = 0.f; g_cc_sum = 0.f;
        g_done_p = 0u;
    }
}

// ---------------- launch ----------------
extern "C" void kernel_launch(void* const* d_in, const int* in_sizes, int n_in,
                              void* d_out, int out_size) {
    const float* pb  = (const float*)d_in[0];
    const float* cc  = (const float*)d_in[1];
    const float* pe  = (const float*)d_in[2];
    const float* pp  = (const float*)d_in[3];
    const float* pt  = (const float*)d_in[4];
    const float* pid = (const float*)d_in[5];
    const int*   tix = (const int*)  d_in[6];
    const float* te  = (const float*)d_in[7];
    const float* tp  = (const float*)d_in[8];
    const float* tt  = (const float*)d_in[9];

    k_hits<<<HBLK, 256>>>(pb, cc, pe, pp, pt, pid, tix, te, tp, tt);
    k_rep<<<HBLK, 256>>>((float*)d_out);
}

// round 14
// speedup vs baseline: 1.0899x; 1.0409x over previous
#include <cuda_runtime.h>
#include <math.h>

#define NHIT 80000
#define KOBJ 512
#define GRID 296               // 2 blocks per SM exactly (148 SMs)
#define THR  256
#define NT   (GRID * THR)      // 75776 base hits
#define NEXTRA (NHIT - NT)     // 4224 = 132 warp-chunks of 32
#define NWARPS (GRID * (THR / 32))   // 2368 global warps
#define WSTRIDE 18             // every 18th warp takes one extra chunk (132 x 18 <= 2368+)
#define EPSF 1e-9f

// ---------------- scratch (device globals; zero at load, reset after use) ----------
__device__ float4 g_hit[NHIT];                 // x, y, q, t_idx (int bits)
__device__ float4 g_A[KOBJ];                   // -2ax, -2ay, |a|^2+1e-6, wrep
__device__ float  g_watt[KOBJ];                // q_a/(cnt+eps)
__device__ float  g_beta_a[KOBJ];
__device__ unsigned long long g_amax[KOBJ];    // packed (beta_bits<<32 | ~idx)
__device__ int    g_cnt[KOBJ];
__device__ float2 g_numden[KOBJ];              // payload num, den
__device__ float  g_pairsum, g_noise_sum, g_noise_cnt, g_cc_sum;
__device__ unsigned g_done_h, g_done_p;

__device__ __forceinline__ float clampb(float b) {
    return fminf(fmaxf(b, 1e-6f), 1.0f - 1e-6f);
}
__device__ __forceinline__ float softclip_f(float x, float c) {
    x = x * (1.0f / c);
    if (x > 1.0f) x = __logf(x + 1.0f);
    return x * c;
}
__device__ __forceinline__ float huber_f(float x, float d) {
    float ax = fabsf(x);
    return ax < d ? x * x : d * d + 2.0f * d * (ax - d);
}
__device__ __forceinline__ float sqapx(float x) {
    float s; asm("sqrt.approx.f32 %0, %1;" : "=f"(s) : "f"(x)); return s;
}

// extra-chunk assignment: global warp g takes chunk g/WSTRIDE if g%WSTRIDE==0
__device__ __forceinline__ int extra_hit_of(int tid) {
    int g = tid >> 5;
    int chunk = g / WSTRIDE;
    if ((g % WSTRIDE) == 0 && chunk < (NEXTRA / 32)) {
        return NT + chunk * 32 + (tid & 31);
    }
    return -1;
}

// ---------------- phase A body: one hit ----------------
__device__ __forceinline__ void process_hit(int i,
        const float* __restrict__ pb,  const float* __restrict__ cc,
        const float* __restrict__ pe,  const float* __restrict__ pp,
        const float* __restrict__ pt,  const float* __restrict__ pid,
        const int*   __restrict__ tix, const float* __restrict__ te,
        const float* __restrict__ tp,  const float* __restrict__ tt,
        float& ns, float& ncnt, float& ccs) {
    float  braw = pb[i];
    int    t    = tix[i];
    float2 ccv  = ((const float2*)cc)[i];
    float  pev  = pe[i];
    float2 ppv  = ((const float2*)pp)[i];
    float  ptv  = pt[i];
    float  tev  = te[i];
    float2 tpv  = ((const float2*)tp)[i];
    float  ttv  = tt[i];
    float2 pid0 = ((const float2*)pid)[3 * i];
    float2 pid1 = ((const float2*)pid)[3 * i + 1];
    float2 pid2 = ((const float2*)pid)[3 * i + 2];

    float beta = clampb(braw);
    float lg = __logf(__fdividef(1.0f + beta, 1.0f - beta));
    float q = fmaf(0.25f * lg, lg, 0.1f);
    g_hit[i] = make_float4(ccv.x, ccv.y, q, __int_as_float(t));
    ccs += ccv.x * ccv.x + ccv.y * ccv.y;

    float ed = fabsf(tev - pev);
    float el = softclip_f(fmaf(10.0f, __expf(-0.1f * ed * ed), 0.01f * ed), 10.0f);
    float dx = tpv.x - ppv.x, dy = tpv.y - ppv.y;
    float pl = softclip_f(huber_f(sqrtf(fmaf(dx, dx, dy * dy) * 0.01f + 0.01f), 10.0f), 3.0f);
    float tl = softclip_f(huber_f(ttv - ptv, 2.0f), 6.0f);
    float s2 = pid0.x * pid0.x + pid0.y * pid0.y + pid1.x * pid1.x
             + pid1.y * pid1.y + pid2.x * pid2.x + pid2.y * pid2.y;
    float cl = 1e-8f * (s2 * (1.0f / 6.0f));
    float payload = el + pl + tl + cl;
    float w = tev > 10.0f ? 1.0f : fmaxf((tev - 0.5f) * (1.0f / 9.5f), 0.0f);
    float pw = beta * w;

    if (t >= 0) {
        atomicAdd(&g_cnt[t], 1);
        unsigned long long key =
            (((unsigned long long)__float_as_uint(beta)) << 32) |
            (unsigned long long)(0xFFFFFFFFu - (unsigned)i);
        atomicMax(&g_amax[t], key);
        asm volatile("red.global.add.v2.f32 [%0], {%1, %2};"
                     :: "l"(&g_numden[t]), "f"(payload * pw), "f"(pw) : "memory");
    } else {
        ns += beta; ncnt += 1.0f;
    }
}

// ---------------- kernel 1: per-hit pass + fused expanded-A-table build ------------
__global__ void __launch_bounds__(THR) k_hits(
        const float* __restrict__ pb,  const float* __restrict__ cc,
        const float* __restrict__ pe,  const float* __restrict__ pp,
        const float* __restrict__ pt,  const float* __restrict__ pid,
        const int*   __restrict__ tix, const float* __restrict__ te,
        const float* __restrict__ tp,  const float* __restrict__ tt) {
    __shared__ unsigned s_last;
    const int tid = blockIdx.x * THR + threadIdx.x;
    float ns = 0.0f, ncnt = 0.0f, ccs = 0.0f;
    process_hit(tid, pb, cc, pe, pp, pt, pid, tix, te, tp, tt, ns, ncnt, ccs);
    int i2 = extra_hit_of(tid);
    if (i2 >= 0)
        process_hit(i2, pb, cc, pe, pp, pt, pid, tix, te, tp, tt, ns, ncnt, ccs);

    #pragma unroll
    for (int o = 16; o > 0; o >>= 1) {
        ns   += __shfl_down_sync(0xFFFFFFFF, ns, o);
        ncnt += __shfl_down_sync(0xFFFFFFFF, ncnt, o);
        ccs  += __shfl_down_sync(0xFFFFFFFF, ccs, o);
    }
    if ((threadIdx.x & 31) == 0) {
        if (ns != 0.0f || ncnt != 0.0f) { atomicAdd(&g_noise_sum, ns); atomicAdd(&g_noise_cnt, ncnt); }
        atomicAdd(&g_cc_sum, ccs);
    }

    // ---- last block builds the expanded A-table ----
    __threadfence();
    if (threadIdx.x == 0) s_last = atomicAdd(&g_done_h, 1u);
    __syncthreads();
    if (s_last != gridDim.x - 1) return;

    #pragma unroll
    for (int kk = 0; kk < 2; kk++) {
        int k = threadIdx.x + kk * THR;
        int c = g_cnt[k];
        if (c > 0) {
            unsigned idx = 0xFFFFFFFFu - (unsigned)(g_amax[k] & 0xFFFFFFFFull);
            float b = clampb(pb[idx]);
            float lg = __logf(__fdividef(1.0f + b, 1.0f - b));
            float qa = fmaf(0.25f * lg, lg, 0.1f);
            float2 ccv = ((const float2*)cc)[idx];
            float fc = (float)c;
            g_A[k] = make_float4(-2.0f * ccv.x, -2.0f * ccv.y,
                                 fmaf(ccv.x, ccv.x, ccv.y * ccv.y) + 1e-6f,
                                 qa / ((float)NHIT - fc + EPSF));
            g_watt[k]   = qa / (fc + EPSF);
            g_beta_a[k] = b;
        } else {
            g_A[k] = make_float4(0.f, 0.f, 1e-6f, 0.f);   // wrep=0: inert
            g_watt[k] = 0.f; g_beta_a[k] = 1.f;
        }
    }
    if (threadIdx.x == 0) g_done_h = 0u;   // reset for next graph replay
}

// ---------------- one hit's flattened N x K contribution ----------------
__device__ __forceinline__ float hit_contrib(int i, const float4* sA) {
    float4 h = g_hit[i];
    const float hx = h.x, hy = h.y;
    const float h2 = fmaf(hx, hx, hy * hy);
    float acc = 0.0f;
    #pragma unroll 8
    for (int k = 0; k < KOBJ; k++) {
        float4 a = sA[k];                // uniform k -> broadcast LDS.128
        float v = fmaf(a.x, hx, a.z);    // -2ax*hx + |a|^2 + eps
        v = fmaf(a.y, hy, v);
        float d2 = v + h2;               // = |h-a|^2 + eps
        float s = __saturatef(1.0f - sqapx(d2));
        acc = fmaf(s, a.w, acc);
    }
    // member terms: remove own-object repulsion (exact cancel), add attraction
    int ti = __float_as_int(h.w);
    if (ti >= 0) {
        float4 a = sA[ti];
        float v = fmaf(a.x, hx, a.z);
        v = fmaf(a.y, hy, v);
        float d2 = v + h2;
        float s = __saturatef(1.0f - sqapx(d2));
        acc = fmaf(-s, a.w, acc);
        acc = fmaf(d2 - 1e-6f, g_watt[ti], acc);
    }
    return h.z * acc;
}

// ---------------- kernel 2: hit-parallel flattened N x K (balanced grid) ----------
__global__ void __launch_bounds__(THR, 4) k_rep(float* __restrict__ out) {
    __shared__ float4 sA[KOBJ];          // 8KB
    __shared__ float s_red[2 * THR];
    __shared__ unsigned s_last;

    const int t = threadIdx.x;
    sA[t]       = g_A[t];
    sA[t + THR] = g_A[t + THR];
    __syncthreads();

    const int tid = blockIdx.x * THR + t;
    float contrib = hit_contrib(tid, sA);
    int i2 = extra_hit_of(tid);
    if (i2 >= 0) contrib += hit_contrib(i2, sA);

    #pragma unroll
    for (int o = 16; o > 0; o >>= 1)
        contrib += __shfl_down_sync(0xFFFFFFFF, contrib, o);
    if ((t & 31) == 0) atomicAdd(&g_pairsum, contrib);

    // ---- last block finalizes + resets scratch for next graph replay ----
    __threadfence();
    if (t == 0) s_last = atomicAdd(&g_done_p, 1u);
    __syncthreads();
    if (s_last != gridDim.x - 1) return;

    float obj = 0.f, has = 0.f;
    #pragma unroll
    for (int kk = 0; kk < 2; kk++) {
        int k = t + kk * THR;
        int c = g_cnt[k];
        if (c > 0) {
            has += 1.0f;
            float2 nd = g_numden[k];
            obj += nd.x / (nd.y + EPSF) + (1.0f - g_beta_a[k]);
        }
        g_amax[k] = 0ull; g_cnt[k] = 0;
        g_numden[k] = make_float2(0.f, 0.f);
    }
    s_red[t] = obj; s_red[t + THR] = has;
    __syncthreads();
    #pragma unroll
    for (int o = THR / 2; o > 0; o >>= 1) {
        if (t < o) { s_red[t] += s_red[t + o]; s_red[t + THR] += s_red[t + THR + o]; }
        __syncthreads();
    }
    if (t == 0) {
        float n_obj = s_red[THR] + EPSF;
        float total = (s_red[0] + g_pairsum) / n_obj
                    + g_noise_sum / (g_noise_cnt + EPSF)
                    + 0.001f * g_cc_sum * (1.0f / (float)(NHIT * 2));
        out[0] = total;
        g_pairsum = 0.f; g_noise_sum = 0.f; g_noise_cnt = 0.f; g_cc_sum = 0.f;
        g_done_p = 0u;
    }
}

// ---------------- launch ----------------
extern "C" void kernel_launch(void* const* d_in, const int* in_sizes, int n_in,
                              void* d_out, int out_size) {
    const float* pb  = (const float*)d_in[0];
    const float* cc  = (const float*)d_in[1];
    const float* pe  = (const float*)d_in[2];
    const float* pp  = (const float*)d_in[3];
    const float* pt  = (const float*)d_in[4];
    const float* pid = (const float*)d_in[5];
    const int*   tix = (const int*)  d_in[6];
    const float* te  = (const float*)d_in[7];
    const float* tp  = (const float*)d_in[8];
    const float* tt  = (const float*)d_in[9];

    k_hits<<<GRID, THR>>>(pb, cc, pe, pp, pt, pid, tix, te, tp, tt);
    k_rep<<<GRID, THR>>>((float*)d_out);
}